// round 8
// baseline (speedup 1.0000x reference)
#include <cuda_runtime.h>
#include <cuda_fp16.h>
#include <math.h>
#include <stdint.h>

#define NROWS 16384
#define DK    2048
#define DOUT  2048

// GEMM tiling: 128x64 CTA tile, 4 warps of 64x32, k32 stages, 4-stage ring
#define BM 128
#define BN 64
#define NST 4
#define ATILE_B (BM * 64)      // 8192 B  (128 rows x 32 fp16 = 64B rows)
#define WTILE_B (BN * 64)      // 4096 B
#define STAGE_B (ATILE_B + 2 * WTILE_B)   // 16384
#define SMEM_BYTES_G (NST * STAGE_B)      // 65536
#define NSTAGES_K (DK / 32)    // 64

// ---------------- device scratch (no allocations allowed) ----------------
__device__ float g_psum[64][DK];
__device__ float g_psq [64][DK];
__device__ float g_scale[DK];
__device__ float g_shift[DK];

__device__ uint4 g_Ah [(size_t)NROWS * DK / 8];   // fp16 normalized x, 64 MB
__device__ uint4 g_W1h[(size_t)DOUT * DK / 8];    // fp16 weights, 8 MB each
__device__ uint4 g_W2h[(size_t)DOUT * DK / 8];

// ---------------- helpers ----------------
__device__ __forceinline__ uint32_t smem_u32(const void* p) {
    uint32_t a;
    asm("{ .reg .u64 t; cvta.to.shared.u64 t, %1; cvt.u32.u64 %0, t; }" : "=r"(a) : "l"(p));
    return a;
}
#define CP16(dst, src) \
    asm volatile("cp.async.cg.shared.global [%0], [%1], 16;" :: "r"(dst), "l"(src))
#define CP_COMMIT() asm volatile("cp.async.commit_group;" ::: "memory")
#define CP_WAIT2()  asm volatile("cp.async.wait_group 2;" ::: "memory")
#define CP_WAIT0()  asm volatile("cp.async.wait_group 0;" ::: "memory")

// swizzled offset inside a tile with 64B rows: 16B chunk XOR'ed by row bits
__device__ __forceinline__ uint32_t swz(int row, int c) {
    return (uint32_t)(row * 64 + ((c ^ ((row >> 1) & 3)) << 4));
}

__device__ __forceinline__ void ldsm4(uint32_t* r, uint32_t addr) {
    asm volatile("ldmatrix.sync.aligned.m8n8.x4.shared.b16 {%0,%1,%2,%3}, [%4];"
                 : "=r"(r[0]), "=r"(r[1]), "=r"(r[2]), "=r"(r[3]) : "r"(addr));
}

__device__ __forceinline__ void mma16816(float* d, const uint32_t* a, const uint32_t* b) {
    asm volatile(
        "mma.sync.aligned.m16n8k16.row.col.f32.f16.f16.f32 "
        "{%0,%1,%2,%3}, {%4,%5,%6,%7}, {%8,%9}, {%0,%1,%2,%3};"
        : "+f"(d[0]), "+f"(d[1]), "+f"(d[2]), "+f"(d[3])
        : "r"(a[0]), "r"(a[1]), "r"(a[2]), "r"(a[3]), "r"(b[0]), "r"(b[1]));
}

// A-style ldmatrix address: mat bit0 -> +8 rows, bit1 -> +k8 chunk
__device__ __forceinline__ uint32_t addrA(uint32_t tbase, int rowbase, int c0, int lid) {
    int m = lid >> 3, r8 = lid & 7;
    int row = rowbase + r8 + (m & 1) * 8;
    int ch  = c0 + (m >> 1);
    return tbase + swz(row, ch);
}
// B-style ldmatrix address: mat bit0 -> +k8 chunk, bit1 -> +8 rows
__device__ __forceinline__ uint32_t addrB(uint32_t tbase, int rowbase, int c0, int lid) {
    int m = lid >> 3, r8 = lid & 7;
    int row = rowbase + r8 + (m >> 1) * 8;
    int ch  = c0 + (m & 1);
    return tbase + swz(row, ch);
}

__device__ __forceinline__ uint32_t pack2h(float a, float b) {
    __half2 h = __floats2half2_rn(a, b);
    return *reinterpret_cast<uint32_t*>(&h);
}

// ---------------- fused: column stats partials + weight fp16 conversion ----------------
__global__ void stats_and_convw(const float* __restrict__ x,
                                const float* __restrict__ w1,
                                const float* __restrict__ w2) {
    const int bx  = blockIdx.x;
    const int tid = threadIdx.x;
    if (bx < 128) {
        const int by = bx >> 1;                       // 256-row group, 0..63
        const int c4 = (bx & 1) * 256 + tid;          // float4 column, 0..511
        const float4* p = (const float4*)x + (size_t)(by * 256) * (DK / 4) + c4;
        float4 s  = make_float4(0.f, 0.f, 0.f, 0.f);
        float4 ss = make_float4(0.f, 0.f, 0.f, 0.f);
#pragma unroll 8
        for (int r = 0; r < 256; ++r) {
            float4 v = p[(size_t)r * (DK / 4)];
            s.x += v.x; s.y += v.y; s.z += v.z; s.w += v.w;
            ss.x += v.x * v.x; ss.y += v.y * v.y;
            ss.z += v.z * v.z; ss.w += v.w * v.w;
        }
        *(float4*)&g_psum[by][c4 * 4] = s;
        *(float4*)&g_psq [by][c4 * 4] = ss;
    } else {
        const int i = (bx - 128) * 256 + tid;         // uint4 index
        const float4* wp1 = (const float4*)w1 + (size_t)i * 2;
        const float4* wp2 = (const float4*)w2 + (size_t)i * 2;
        float4 a0 = wp1[0], a1 = wp1[1];
        float4 b0 = wp2[0], b1 = wp2[1];
        uint4 h1, h2;
        h1.x = pack2h(a0.x, a0.y); h1.y = pack2h(a0.z, a0.w);
        h1.z = pack2h(a1.x, a1.y); h1.w = pack2h(a1.z, a1.w);
        h2.x = pack2h(b0.x, b0.y); h2.y = pack2h(b0.z, b0.w);
        h2.z = pack2h(b1.x, b1.y); h2.w = pack2h(b1.z, b1.w);
        g_W1h[i] = h1;
        g_W2h[i] = h2;
    }
}

__global__ void colstats_final(const float* __restrict__ gamma,
                               const float* __restrict__ beta) {
    int col = blockIdx.x * 256 + threadIdx.x;
    float s = 0.f, ss = 0.f;
#pragma unroll
    for (int c = 0; c < 64; ++c) { s += g_psum[c][col]; ss += g_psq[c][col]; }
    float mean = s / (float)NROWS;
    float var  = (ss - s * mean) / (float)(NROWS - 1);   // ddof=1 (torch.std)
    float inv  = rsqrtf(var + 1e-8f);
    float sc   = gamma[col] * inv;
    g_scale[col] = sc;
    g_shift[col] = beta[col] - mean * sc;
}

// x -> normalized fp16
__global__ void convert_x_kernel(const float* __restrict__ x) {
    int i = blockIdx.x * 256 + threadIdx.x;            // uint4 index (8 elems)
    int col = (i * 8) & (DK - 1);
    const float4* xp = (const float4*)x + (size_t)i * 2;
    float4 v0 = xp[0], v1 = xp[1];
    float4 sc0 = *(const float4*)(g_scale + col);
    float4 sc1 = *(const float4*)(g_scale + col + 4);
    float4 sh0 = *(const float4*)(g_shift + col);
    float4 sh1 = *(const float4*)(g_shift + col + 4);
    uint4 hi;
    hi.x = pack2h(v0.x * sc0.x + sh0.x, v0.y * sc0.y + sh0.y);
    hi.y = pack2h(v0.z * sc0.z + sh0.z, v0.w * sc0.w + sh0.w);
    hi.z = pack2h(v1.x * sc1.x + sh1.x, v1.y * sc1.y + sh1.y);
    hi.w = pack2h(v1.z * sc1.z + sh1.z, v1.w * sc1.w + sh1.w);
    g_Ah[i] = hi;
}

__device__ __forceinline__ float clamp_small(float t) {
    const float EPS = 1e-12f;
    if (t >= 0.f && t <  EPS) return  EPS;
    if (t <  0.f && t > -EPS) return -EPS;
    return t;
}

// ---------------- fused dual GEMM (fp16 mma.sync, 4 warps x 64x32) ----------------
__global__ __launch_bounds__(128, 2)
void dual_gemm_mma(const float* __restrict__ b1v, const float* __restrict__ b2v,
                   float* __restrict__ out) {
    extern __shared__ __align__(128) char smem[];
    const uint32_t sbase = smem_u32(smem);

    const int tid = threadIdx.x;
    const int lid = tid & 31;
    const int wid = tid >> 5;
    const int wm  = wid & 1;        // 2 warps along M (64 rows each)
    const int wn  = wid >> 1;       // 2 warps along N (32 cols each)

    // rasterize: 8 n-tiles per group, m fastest -> wave shares A rows & W cols in L2
    const int id  = blockIdx.x;
    const int grp = id >> 10;
    const int rem = id & 1023;
    const int m0  = (rem >> 3) * BM;
    const int n0  = ((grp << 3) | (rem & 7)) * BN;

    const char* srcA  = (const char*)g_Ah  + (size_t)m0 * 4096;
    const char* srcW1 = (const char*)g_W1h + (size_t)n0 * 4096;
    const char* srcW2 = (const char*)g_W2h + (size_t)n0 * 4096;

    // cp.async coords: A row = tid (0..127), 4 chunks; W row = tid/2 (0..63), 2 chunks each
    const int wrow = tid >> 1, wc0 = (tid & 1) * 2;

    auto issue = [&](int bi, int kb) {
        const uint32_t st = sbase + bi * STAGE_B;
        const char* sA = srcA + (size_t)tid * 4096 + kb;
#pragma unroll
        for (int j = 0; j < 4; ++j)
            CP16(st + swz(tid, j), sA + j * 16);
        const size_t off = (size_t)wrow * 4096 + kb + wc0 * 16;
        const uint32_t d = st + ATILE_B;
#pragma unroll
        for (int j = 0; j < 2; ++j) {
            CP16(d +           swz(wrow, wc0 + j), srcW1 + off + j * 16);
            CP16(d + WTILE_B + swz(wrow, wc0 + j), srcW2 + off + j * 16);
        }
    };

    float acc1[4][4][4];
    float acc2[4][4][4];
#pragma unroll
    for (int mf = 0; mf < 4; ++mf)
#pragma unroll
        for (int ni = 0; ni < 4; ++ni)
#pragma unroll
            for (int j = 0; j < 4; ++j) { acc1[mf][ni][j] = 0.f; acc2[mf][ni][j] = 0.f; }

    issue(0, 0);   CP_COMMIT();
    issue(1, 64);  CP_COMMIT();
    issue(2, 128); CP_COMMIT();

    for (int i = 0; i < NSTAGES_K; ++i) {
        CP_WAIT2();
        __syncthreads();   // orders compute(i-1) before writes into stage (i-1)%4 below
        if (i + 3 < NSTAGES_K) issue((i + 3) & 3, (i + 3) * 64);
        CP_COMMIT();

        const uint32_t st  = sbase + (i & 3) * STAGE_B;
        const uint32_t stW = st + ATILE_B;
#pragma unroll
        for (int ks = 0; ks < 2; ++ks) {
            const int c0 = ks * 2;
            uint32_t ah[4][4];
#pragma unroll
            for (int mf = 0; mf < 4; ++mf)
                ldsm4(ah[mf], addrA(st, wm * 64 + mf * 16, c0, lid));
            uint32_t w1f[8], w2f[8];
            ldsm4(&w1f[0], addrB(stW,           wn * 32,      c0, lid));
            ldsm4(&w1f[4], addrB(stW,           wn * 32 + 16, c0, lid));
            ldsm4(&w2f[0], addrB(stW + WTILE_B, wn * 32,      c0, lid));
            ldsm4(&w2f[4], addrB(stW + WTILE_B, wn * 32 + 16, c0, lid));
#pragma unroll
            for (int mf = 0; mf < 4; ++mf) {
#pragma unroll
                for (int ni = 0; ni < 4; ++ni) {
                    mma16816(acc1[mf][ni], ah[mf], &w1f[ni * 2]);   // A*W1
                    mma16816(acc2[mf][ni], ah[mf], &w2f[ni * 2]);   // A*W2
                }
            }
        }
        // no tail sync: head sync of next iteration provides the WAR ordering
    }
    CP_WAIT0();

    // epilogue: bias + sigmoid + clamp + product
#pragma unroll
    for (int mf = 0; mf < 4; ++mf) {
        const int mrow = m0 + wm * 64 + mf * 16 + (lid >> 2);
#pragma unroll
        for (int ni = 0; ni < 4; ++ni) {
            const int col = n0 + wn * 32 + ni * 8 + (lid & 3) * 2;
            const float b1x = b1v[col], b1y = b1v[col + 1];
            const float b2x = b2v[col], b2y = b2v[col + 1];

            float h1, z, s;
            float2 r;
            h1 = clamp_small(acc1[mf][ni][0] + b1x);
            z  = acc2[mf][ni][0] + b2x;
            s  = clamp_small(1.0f / (1.0f + __expf(-z)));
            r.x = h1 * s;
            h1 = clamp_small(acc1[mf][ni][1] + b1y);
            z  = acc2[mf][ni][1] + b2y;
            s  = clamp_small(1.0f / (1.0f + __expf(-z)));
            r.y = h1 * s;
            *(float2*)(out + (size_t)mrow * DOUT + col) = r;

            h1 = clamp_small(acc1[mf][ni][2] + b1x);
            z  = acc2[mf][ni][2] + b2x;
            s  = clamp_small(1.0f / (1.0f + __expf(-z)));
            r.x = h1 * s;
            h1 = clamp_small(acc1[mf][ni][3] + b1y);
            z  = acc2[mf][ni][3] + b2y;
            s  = clamp_small(1.0f / (1.0f + __expf(-z)));
            r.y = h1 * s;
            *(float2*)(out + (size_t)(mrow + 8) * DOUT + col) = r;
        }
    }
}

// ---------------- launch ----------------
extern "C" void kernel_launch(void* const* d_in, const int* in_sizes, int n_in,
                              void* d_out, int out_size) {
    const float* x     = (const float*)d_in[0];
    const float* w1    = (const float*)d_in[1];
    const float* b1    = (const float*)d_in[2];
    const float* w2    = (const float*)d_in[3];
    const float* b2    = (const float*)d_in[4];
    const float* gamma = (const float*)d_in[5];
    const float* beta  = (const float*)d_in[6];
    float* out = (float*)d_out;

    cudaFuncSetAttribute(dual_gemm_mma, cudaFuncAttributeMaxDynamicSharedMemorySize,
                         SMEM_BYTES_G);

    stats_and_convw<<<128 + (DOUT * DK / 8) / 256, 256>>>(x, w1, w2);
    colstats_final<<<DK / 256, 256>>>(gamma, beta);
    convert_x_kernel<<<(NROWS * (DK / 8)) / 256, 256>>>(x);

    const int grid = (NROWS / BM) * (DOUT / BN);   // 4096
    dual_gemm_mma<<<grid, 128, SMEM_BYTES_G>>>(b1, b2, out);
}

// round 9
// speedup vs baseline: 1.4831x; 1.4831x over previous
#include <cuda_runtime.h>
#include <cuda_fp16.h>
#include <math.h>
#include <stdint.h>

#define NROWS 16384
#define DK    2048
#define DOUT  2048

// GEMM tiling: 128x64 CTA tile, 8 warps of 32x32, k32 stages, 5-stage ring
#define BM 128
#define BN 64
#define NST 5
#define ATILE_B (BM * 64)      // 8192 B  (128 rows x 32 fp16 = 64B rows)
#define WTILE_B (BN * 64)      // 4096 B
#define STAGE_B (ATILE_B + 2 * WTILE_B)   // 16384
#define SMEM_BYTES_G (NST * STAGE_B)      // 81920
#define NSTAGES_K (DK / 32)    // 64

// ---------------- device scratch (no allocations allowed) ----------------
__device__ float g_psum[64][DK];
__device__ float g_psq [64][DK];
__device__ float g_scale[DK];
__device__ float g_shift[DK];

__device__ uint4 g_Ah [(size_t)NROWS * DK / 8];   // fp16 normalized x, 64 MB
__device__ uint4 g_W1h[(size_t)DOUT * DK / 8];    // fp16 weights, 8 MB each
__device__ uint4 g_W2h[(size_t)DOUT * DK / 8];

// ---------------- helpers ----------------
__device__ __forceinline__ uint32_t smem_u32(const void* p) {
    uint32_t a;
    asm("{ .reg .u64 t; cvta.to.shared.u64 t, %1; cvt.u32.u64 %0, t; }" : "=r"(a) : "l"(p));
    return a;
}
#define CP16(dst, src) \
    asm volatile("cp.async.cg.shared.global [%0], [%1], 16;" :: "r"(dst), "l"(src))
#define CP_COMMIT() asm volatile("cp.async.commit_group;" ::: "memory")
#define CP_WAIT3()  asm volatile("cp.async.wait_group 3;" ::: "memory")
#define CP_WAIT0()  asm volatile("cp.async.wait_group 0;" ::: "memory")

// swizzled offset inside a tile with 64B rows: 16B chunk XOR'ed by row bits
__device__ __forceinline__ uint32_t swz(int row, int c) {
    return (uint32_t)(row * 64 + ((c ^ ((row >> 1) & 3)) << 4));
}

__device__ __forceinline__ void ldsm4(uint32_t* r, uint32_t addr) {
    asm volatile("ldmatrix.sync.aligned.m8n8.x4.shared.b16 {%0,%1,%2,%3}, [%4];"
                 : "=r"(r[0]), "=r"(r[1]), "=r"(r[2]), "=r"(r[3]) : "r"(addr));
}

__device__ __forceinline__ void mma16816(float* d, const uint32_t* a, const uint32_t* b) {
    asm volatile(
        "mma.sync.aligned.m16n8k16.row.col.f32.f16.f16.f32 "
        "{%0,%1,%2,%3}, {%4,%5,%6,%7}, {%8,%9}, {%0,%1,%2,%3};"
        : "+f"(d[0]), "+f"(d[1]), "+f"(d[2]), "+f"(d[3])
        : "r"(a[0]), "r"(a[1]), "r"(a[2]), "r"(a[3]), "r"(b[0]), "r"(b[1]));
}

// A-style ldmatrix address: mat bit0 -> +8 rows, bit1 -> +k8 chunk
__device__ __forceinline__ uint32_t addrA(uint32_t tbase, int rowbase, int c0, int lid) {
    int m = lid >> 3, r8 = lid & 7;
    int row = rowbase + r8 + (m & 1) * 8;
    int ch  = c0 + (m >> 1);
    return tbase + swz(row, ch);
}
// B-style ldmatrix address: mat bit0 -> +k8 chunk, bit1 -> +8 rows
__device__ __forceinline__ uint32_t addrB(uint32_t tbase, int rowbase, int c0, int lid) {
    int m = lid >> 3, r8 = lid & 7;
    int row = rowbase + r8 + (m >> 1) * 8;
    int ch  = c0 + (m & 1);
    return tbase + swz(row, ch);
}

__device__ __forceinline__ uint32_t pack2h(float a, float b) {
    __half2 h = __floats2half2_rn(a, b);
    return *reinterpret_cast<uint32_t*>(&h);
}

// ---------------- fused: column stats partials + weight fp16 conversion ----------------
__global__ void stats_and_convw(const float* __restrict__ x,
                                const float* __restrict__ w1,
                                const float* __restrict__ w2) {
    const int bx  = blockIdx.x;
    const int tid = threadIdx.x;
    if (bx < 128) {
        const int by = bx >> 1;                       // 256-row group, 0..63
        const int c4 = (bx & 1) * 256 + tid;          // float4 column, 0..511
        const float4* p = (const float4*)x + (size_t)(by * 256) * (DK / 4) + c4;
        float4 s  = make_float4(0.f, 0.f, 0.f, 0.f);
        float4 ss = make_float4(0.f, 0.f, 0.f, 0.f);
#pragma unroll 8
        for (int r = 0; r < 256; ++r) {
            float4 v = p[(size_t)r * (DK / 4)];
            s.x += v.x; s.y += v.y; s.z += v.z; s.w += v.w;
            ss.x += v.x * v.x; ss.y += v.y * v.y;
            ss.z += v.z * v.z; ss.w += v.w * v.w;
        }
        *(float4*)&g_psum[by][c4 * 4] = s;
        *(float4*)&g_psq [by][c4 * 4] = ss;
    } else {
        const int i = (bx - 128) * 256 + tid;         // uint4 index
        const float4* wp1 = (const float4*)w1 + (size_t)i * 2;
        const float4* wp2 = (const float4*)w2 + (size_t)i * 2;
        float4 a0 = wp1[0], a1 = wp1[1];
        float4 b0 = wp2[0], b1 = wp2[1];
        uint4 h1, h2;
        h1.x = pack2h(a0.x, a0.y); h1.y = pack2h(a0.z, a0.w);
        h1.z = pack2h(a1.x, a1.y); h1.w = pack2h(a1.z, a1.w);
        h2.x = pack2h(b0.x, b0.y); h2.y = pack2h(b0.z, b0.w);
        h2.z = pack2h(b1.x, b1.y); h2.w = pack2h(b1.z, b1.w);
        g_W1h[i] = h1;
        g_W2h[i] = h2;
    }
}

__global__ void colstats_final(const float* __restrict__ gamma,
                               const float* __restrict__ beta) {
    int col = blockIdx.x * 256 + threadIdx.x;
    float s = 0.f, ss = 0.f;
#pragma unroll
    for (int c = 0; c < 64; ++c) { s += g_psum[c][col]; ss += g_psq[c][col]; }
    float mean = s / (float)NROWS;
    float var  = (ss - s * mean) / (float)(NROWS - 1);   // ddof=1 (torch.std)
    float inv  = rsqrtf(var + 1e-8f);
    float sc   = gamma[col] * inv;
    g_scale[col] = sc;
    g_shift[col] = beta[col] - mean * sc;
}

// x -> normalized fp16
__global__ void convert_x_kernel(const float* __restrict__ x) {
    int i = blockIdx.x * 256 + threadIdx.x;            // uint4 index (8 elems)
    int col = (i * 8) & (DK - 1);
    const float4* xp = (const float4*)x + (size_t)i * 2;
    float4 v0 = xp[0], v1 = xp[1];
    float4 sc0 = *(const float4*)(g_scale + col);
    float4 sc1 = *(const float4*)(g_scale + col + 4);
    float4 sh0 = *(const float4*)(g_shift + col);
    float4 sh1 = *(const float4*)(g_shift + col + 4);
    uint4 hi;
    hi.x = pack2h(v0.x * sc0.x + sh0.x, v0.y * sc0.y + sh0.y);
    hi.y = pack2h(v0.z * sc0.z + sh0.z, v0.w * sc0.w + sh0.w);
    hi.z = pack2h(v1.x * sc1.x + sh1.x, v1.y * sc1.y + sh1.y);
    hi.w = pack2h(v1.z * sc1.z + sh1.z, v1.w * sc1.w + sh1.w);
    g_Ah[i] = hi;
}

__device__ __forceinline__ float clamp_small(float t) {
    const float EPS = 1e-12f;
    if (t >= 0.f && t <  EPS) return  EPS;
    if (t <  0.f && t > -EPS) return -EPS;
    return t;
}

// ---------------- fused dual GEMM (plain fp16 mma.sync, 8 warps x 32x32) ----------------
__global__ __launch_bounds__(256, 2)
void dual_gemm_mma(const float* __restrict__ b1v, const float* __restrict__ b2v,
                   float* __restrict__ out) {
    extern __shared__ __align__(128) char smem[];
    const uint32_t sbase = smem_u32(smem);

    const int tid = threadIdx.x;
    const int lid = tid & 31;
    const int wid = tid >> 5;
    const int wm  = wid & 3;        // 4 warps along M
    const int wn  = wid >> 2;       // 2 warps along N

    // rasterize: 8 n-tiles per group, m fastest -> wave shares A rows & W cols in L2
    const int id  = blockIdx.x;
    const int grp = id >> 10;
    const int rem = id & 1023;
    const int m0  = (rem >> 3) * BM;
    const int n0  = ((grp << 3) | (rem & 7)) * BN;

    const char* srcA  = (const char*)g_Ah  + (size_t)m0 * 4096;
    const char* srcW1 = (const char*)g_W1h + (size_t)n0 * 4096;
    const char* srcW2 = (const char*)g_W2h + (size_t)n0 * 4096;

    const int arow0 = tid >> 2;        // 0..63, A covers 128 rows in two passes
    const int ac    = tid & 3;

    auto issueA = [&](int bi, int kb) {
        const uint32_t st = sbase + bi * STAGE_B;
#pragma unroll
        for (int j = 0; j < 2; ++j) {
            int row = arow0 + 64 * j;
            CP16(st + swz(row, ac), srcA + (size_t)row * 4096 + kb + ac * 16);
        }
    };
    auto issueW = [&](int bi, int kb) {
        const uint32_t st = sbase + bi * STAGE_B;
        uint32_t d = st + ATILE_B + swz(arow0, ac);
        const size_t off = (size_t)arow0 * 4096 + kb + ac * 16;
        CP16(d,           srcW1 + off);
        CP16(d + WTILE_B, srcW2 + off);
    };

    float acc1[2][4][4];
    float acc2[2][4][4];
#pragma unroll
    for (int mi = 0; mi < 2; ++mi)
#pragma unroll
        for (int ni = 0; ni < 4; ++ni)
#pragma unroll
            for (int j = 0; j < 4; ++j) { acc1[mi][ni][j] = 0.f; acc2[mi][ni][j] = 0.f; }

    // prologue: 4 stages in flight
#pragma unroll
    for (int p = 0; p < 4; ++p) {
        issueA(p, p * 64);
        issueW(p, p * 64);
        CP_COMMIT();
    }

    for (int i = 0; i < NSTAGES_K; ++i) {
        CP_WAIT3();
        __syncthreads();   // orders compute(i-1) before writes into stage (i-1)%5 below
        const int   nb = (i + 4) % NST;
        const bool  pf = (i + 4 < NSTAGES_K);
        const uint32_t st  = sbase + (i % NST) * STAGE_B;
        const uint32_t stW = st + ATILE_B;

        if (pf) issueA(nb, (i + 4) * 64);

        // ---- ks = 0 ----
        {
            uint32_t ah[2][4];
            ldsm4(ah[0], addrA(st, wm * 32,      0, lid));
            ldsm4(ah[1], addrA(st, wm * 32 + 16, 0, lid));
            uint32_t w[2][8];
            ldsm4(&w[0][0], addrB(stW,           wn * 32,      0, lid));
            ldsm4(&w[0][4], addrB(stW,           wn * 32 + 16, 0, lid));
            ldsm4(&w[1][0], addrB(stW + WTILE_B, wn * 32,      0, lid));
            ldsm4(&w[1][4], addrB(stW + WTILE_B, wn * 32 + 16, 0, lid));
#pragma unroll
            for (int mi = 0; mi < 2; ++mi)
#pragma unroll
                for (int ni = 0; ni < 4; ++ni) {
                    mma16816(acc1[mi][ni], ah[mi], &w[0][ni * 2]);
                    mma16816(acc2[mi][ni], ah[mi], &w[1][ni * 2]);
                }
        }

        if (pf) issueW(nb, (i + 4) * 64);
        CP_COMMIT();

        // ---- ks = 1 ----
        {
            uint32_t ah[2][4];
            ldsm4(ah[0], addrA(st, wm * 32,      2, lid));
            ldsm4(ah[1], addrA(st, wm * 32 + 16, 2, lid));
            uint32_t w[2][8];
            ldsm4(&w[0][0], addrB(stW,           wn * 32,      2, lid));
            ldsm4(&w[0][4], addrB(stW,           wn * 32 + 16, 2, lid));
            ldsm4(&w[1][0], addrB(stW + WTILE_B, wn * 32,      2, lid));
            ldsm4(&w[1][4], addrB(stW + WTILE_B, wn * 32 + 16, 2, lid));
#pragma unroll
            for (int mi = 0; mi < 2; ++mi)
#pragma unroll
                for (int ni = 0; ni < 4; ++ni) {
                    mma16816(acc1[mi][ni], ah[mi], &w[0][ni * 2]);
                    mma16816(acc2[mi][ni], ah[mi], &w[1][ni * 2]);
                }
        }
        // no tail sync: head sync of next iteration provides the WAR ordering
    }
    CP_WAIT0();

    // epilogue: bias + sigmoid + clamp + product
#pragma unroll
    for (int mi = 0; mi < 2; ++mi) {
        const int mrow = m0 + wm * 32 + mi * 16 + (lid >> 2);
#pragma unroll
        for (int ni = 0; ni < 4; ++ni) {
            const int col = n0 + wn * 32 + ni * 8 + (lid & 3) * 2;
            const float b1x = b1v[col], b1y = b1v[col + 1];
            const float b2x = b2v[col], b2y = b2v[col + 1];

            float h1, z, s;
            float2 r;
            h1 = clamp_small(acc1[mi][ni][0] + b1x);
            z  = acc2[mi][ni][0] + b2x;
            s  = clamp_small(1.0f / (1.0f + __expf(-z)));
            r.x = h1 * s;
            h1 = clamp_small(acc1[mi][ni][1] + b1y);
            z  = acc2[mi][ni][1] + b2y;
            s  = clamp_small(1.0f / (1.0f + __expf(-z)));
            r.y = h1 * s;
            *(float2*)(out + (size_t)mrow * DOUT + col) = r;

            h1 = clamp_small(acc1[mi][ni][2] + b1x);
            z  = acc2[mi][ni][2] + b2x;
            s  = clamp_small(1.0f / (1.0f + __expf(-z)));
            r.x = h1 * s;
            h1 = clamp_small(acc1[mi][ni][3] + b1y);
            z  = acc2[mi][ni][3] + b2y;
            s  = clamp_small(1.0f / (1.0f + __expf(-z)));
            r.y = h1 * s;
            *(float2*)(out + (size_t)(mrow + 8) * DOUT + col) = r;
        }
    }
}

// ---------------- launch ----------------
extern "C" void kernel_launch(void* const* d_in, const int* in_sizes, int n_in,
                              void* d_out, int out_size) {
    const float* x     = (const float*)d_in[0];
    const float* w1    = (const float*)d_in[1];
    const float* b1    = (const float*)d_in[2];
    const float* w2    = (const float*)d_in[3];
    const float* b2    = (const float*)d_in[4];
    const float* gamma = (const float*)d_in[5];
    const float* beta  = (const float*)d_in[6];
    float* out = (float*)d_out;

    cudaFuncSetAttribute(dual_gemm_mma, cudaFuncAttributeMaxDynamicSharedMemorySize,
                         SMEM_BYTES_G);

    stats_and_convw<<<128 + (DOUT * DK / 8) / 256, 256>>>(x, w1, w2);
    colstats_final<<<DK / 256, 256>>>(gamma, beta);
    convert_x_kernel<<<(NROWS * (DK / 8)) / 256, 256>>>(x);

    const int grid = (NROWS / BM) * (DOUT / BN);   // 4096
    dual_gemm_mma<<<grid, 256, SMEM_BYTES_G>>>(b1, b2, out);
}